// round 5
// baseline (speedup 1.0000x reference)
#include <cuda_runtime.h>
#include <math_constants.h>

// Problem constants (fixed by the reference setup)
#define BB   4
#define NN   32768
#define KK   16
#define DD   8
#define TOT  (BB * NN * KK)        // 2,097,152 per channel
#define GRPS (TOT / 4)             // 524,288 groups of 4 along K
#define TPB  256
#define NBLK 592                   // 148 SMs x 4 blocks: guaranteed co-resident
#define NT   (NBLK * TPB)          // 151,552 threads
#define EPSF 1e-6f

// Device-global scratch (no allocation allowed)
__device__ double g_sum[DD];
__device__ double g_sqs[DD];
__device__ float  g_scale[DD];
__device__ float  g_shift[DD];
__device__ unsigned int g_ctrA;
__device__ unsigned int g_ctrB;
__device__ volatile unsigned int g_relA;
__device__ volatile unsigned int g_relB;
__device__ float4 g_c4[BB * NN];   // repacked coords (2 MB, L2-resident)

__device__ __forceinline__ int clamp_idx(int v) {
    v = v < 0 ? 0 : v;
    return v >= NN ? NN - 1 : v;
}

__global__ void __launch_bounds__(TPB, 4) k_fused(
    const float* __restrict__ coords,      // (B,N,3)
    const float* __restrict__ features,    // (B,D,N,1)
    const int* __restrict__ knn_idx,       // (B,N,K) int32
    const float* __restrict__ knn_dist,    // (B,N,K)
    const int* __restrict__ mask,          // (B,N)
    const float* __restrict__ conv_w,      // (D,10)
    const float* __restrict__ conv_b,      // (D)
    const float* __restrict__ bn_gamma,
    const float* __restrict__ bn_beta,
    float* __restrict__ out)               // (B,2D,N,K)
{
    __shared__ float s_wn0[DD], s_wn1[DD], s_wn2[DD], s_wdd[DD];
    __shared__ float s_wc0[DD], s_wc1[DD], s_wc2[DD], s_b[DD];
    __shared__ float s_sc[DD], s_sh[DD];
    __shared__ float s_part[TPB / 32][2 * DD];

    const int tid = threadIdx.x;
    const int gid = blockIdx.x * TPB + tid;

    // ---- Phase 0: fold weights to shared; zero sums (block 0); repack coords
    if (tid < DD) {
        const float* w = conv_w + tid * 10;
        float w0=w[0], w1=w[1], w2=w[2], w3=w[3], w4=w[4];
        float w5=w[5], w6=w[6], w7=w[7], w8=w[8];
        s_wn0[tid] = w3 - w6;  s_wn1[tid] = w4 - w7;  s_wn2[tid] = w5 - w8;
        s_wdd[tid] = w[9];
        s_wc0[tid] = w0 + w6;  s_wc1[tid] = w1 + w7;  s_wc2[tid] = w2 + w8;
        s_b[tid]   = conv_b[tid];
    }
    if (blockIdx.x == 0 && tid < DD) {
        g_sum[tid] = 0.0;
        g_sqs[tid] = 0.0;
    }
    if (gid < BB * NN) {
        float x = coords[3 * gid + 0];
        float y = coords[3 * gid + 1];
        float z = coords[3 * gid + 2];
        g_c4[gid] = make_float4(x, y, z, 0.f);
    }

    // ---- Barrier A (monotone counters: replay-safe, no reset needed)
    __threadfence();
    __syncthreads();
    if (tid == 0) {
        unsigned prev = atomicAdd(&g_ctrA, 1u);
        unsigned target = prev - (prev % NBLK) + NBLK;
        if (prev % NBLK == NBLK - 1) {
            g_relA = target;
        } else {
            while (g_relA < target) __nanosleep(64);
        }
    }
    __syncthreads();

    // ---- Phase 1: grid-stride BN statistics
    float s[DD], q[DD];
#pragma unroll
    for (int d = 0; d < DD; d++) { s[d] = 0.f; q[d] = 0.f; }

#pragma unroll 1
    for (int g = gid; g < GRPS; g += NT) {
        const int e0 = g * 4;
        const int b  = e0 >> 19;            // / (NN*KK) = 2^19
        const int rm = e0 & ((NN * KK) - 1);
        const int n  = rm >> 4;             // / KK

        const float4 c = g_c4[b * NN + n];

        int4 iv = *reinterpret_cast<const int4*>(knn_idx + e0);
        int j0 = clamp_idx(iv.x), j1 = clamp_idx(iv.y);
        int j2 = clamp_idx(iv.z), j3 = clamp_idx(iv.w);

        float4 d4 = *reinterpret_cast<const float4*>(knn_dist + e0);
        float dv0 = d4.x, dv1 = d4.y, dv2 = d4.z, dv3 = d4.w;
        if (mask[b * NN + n] == 0) {
            dv0 = dv1 = dv2 = dv3 = CUDART_INF_F;
        }

        float4 p0 = g_c4[b * NN + j0];
        float4 p1 = g_c4[b * NN + j1];
        float4 p2 = g_c4[b * NN + j2];
        float4 p3 = g_c4[b * NN + j3];

#pragma unroll
        for (int d = 0; d < DD; d++) {
            float base = s_b[d] + s_wc0[d] * c.x + s_wc1[d] * c.y + s_wc2[d] * c.z;
            float x0 = base + s_wn0[d]*p0.x + s_wn1[d]*p0.y + s_wn2[d]*p0.z + s_wdd[d]*dv0;
            float x1 = base + s_wn0[d]*p1.x + s_wn1[d]*p1.y + s_wn2[d]*p1.z + s_wdd[d]*dv1;
            float x2 = base + s_wn0[d]*p2.x + s_wn1[d]*p2.y + s_wn2[d]*p2.z + s_wdd[d]*dv2;
            float x3 = base + s_wn0[d]*p3.x + s_wn1[d]*p3.y + s_wn2[d]*p3.z + s_wdd[d]*dv3;
            s[d] += (x0 + x1) + (x2 + x3);
            q[d] = fmaf(x0, x0, q[d]);
            q[d] = fmaf(x1, x1, q[d]);
            q[d] = fmaf(x2, x2, q[d]);
            q[d] = fmaf(x3, x3, q[d]);
        }
    }

    // block reduction -> double atomics
#pragma unroll
    for (int d = 0; d < DD; d++) {
#pragma unroll
        for (int o = 16; o > 0; o >>= 1) {
            s[d] += __shfl_xor_sync(0xFFFFFFFFu, s[d], o);
            q[d] += __shfl_xor_sync(0xFFFFFFFFu, q[d], o);
        }
    }
    const int warp = tid >> 5;
    const int lane = tid & 31;
    if (lane == 0) {
#pragma unroll
        for (int d = 0; d < DD; d++) {
            s_part[warp][d]      = s[d];
            s_part[warp][DD + d] = q[d];
        }
    }
    __syncthreads();
    if (tid < 2 * DD) {
        float acc = 0.f;
#pragma unroll
        for (int w = 0; w < TPB / 32; w++) acc += s_part[w][tid];
        if (tid < DD)
            atomicAdd(&g_sum[tid], (double)acc);
        else
            atomicAdd(&g_sqs[tid - DD], (double)acc);
    }

    // ---- Barrier B: last arriver finalizes BN affine params (single thread FP64)
    __threadfence();
    __syncthreads();
    if (tid == 0) {
        unsigned prev = atomicAdd(&g_ctrB, 1u);
        unsigned target = prev - (prev % NBLK) + NBLK;
        if (prev % NBLK == NBLK - 1) {
            for (int d = 0; d < DD; d++) {
                double sm = ((volatile double*)g_sum)[d];
                double sq = ((volatile double*)g_sqs)[d];
                double mean = sm * (1.0 / (double)TOT);
                double var  = sq * (1.0 / (double)TOT) - mean * mean;
                float rstd  = rsqrtf((float)var + EPSF);
                float sc    = bn_gamma[d] * rstd;
                g_scale[d]  = sc;
                g_shift[d]  = bn_beta[d] - (float)mean * sc;
            }
            __threadfence();
            g_relB = target;
        } else {
            while (g_relB < target) __nanosleep(64);
        }
    }
    __syncthreads();
    if (tid < DD) {
        s_sc[tid] = ((volatile float*)g_scale)[tid];
        s_sh[tid] = ((volatile float*)g_shift)[tid];
    }
    __syncthreads();

    // ---- Phase 2: write the 128 MB output (pure fp32)
#pragma unroll 1
    for (int g = gid; g < GRPS; g += NT) {
        const int e0 = g * 4;
        const int b  = e0 >> 19;
        const int rm = e0 & ((NN * KK) - 1);
        const int n  = rm >> 4;
        const int k0 = rm & (KK - 1);

        const float4 c = g_c4[b * NN + n];

        int4 iv = *reinterpret_cast<const int4*>(knn_idx + e0);
        int j0 = clamp_idx(iv.x), j1 = clamp_idx(iv.y);
        int j2 = clamp_idx(iv.z), j3 = clamp_idx(iv.w);

        float4 d4 = *reinterpret_cast<const float4*>(knn_dist + e0);
        float dv0 = d4.x, dv1 = d4.y, dv2 = d4.z, dv3 = d4.w;
        if (mask[b * NN + n] == 0) {
            dv0 = dv1 = dv2 = dv3 = CUDART_INF_F;
        }

        float4 p0 = g_c4[b * NN + j0];
        float4 p1 = g_c4[b * NN + j1];
        float4 p2 = g_c4[b * NN + j2];
        float4 p3 = g_c4[b * NN + j3];

        const size_t obase = ((size_t)b * (2 * DD)) * NN * KK + (size_t)n * KK + k0;
#pragma unroll
        for (int d = 0; d < DD; d++) {
            float base = s_b[d] + s_wc0[d] * c.x + s_wc1[d] * c.y + s_wc2[d] * c.z;
            float x0 = base + s_wn0[d]*p0.x + s_wn1[d]*p0.y + s_wn2[d]*p0.z + s_wdd[d]*dv0;
            float x1 = base + s_wn0[d]*p1.x + s_wn1[d]*p1.y + s_wn2[d]*p1.z + s_wdd[d]*dv1;
            float x2 = base + s_wn0[d]*p2.x + s_wn1[d]*p2.y + s_wn2[d]*p2.z + s_wdd[d]*dv2;
            float x3 = base + s_wn0[d]*p3.x + s_wn1[d]*p3.y + s_wn2[d]*p3.z + s_wdd[d]*dv3;
            float4 o;
            o.x = fmaxf(fmaf(x0, s_sc[d], s_sh[d]), 0.f);
            o.y = fmaxf(fmaf(x1, s_sc[d], s_sh[d]), 0.f);
            o.z = fmaxf(fmaf(x2, s_sc[d], s_sh[d]), 0.f);
            o.w = fmaxf(fmaf(x3, s_sc[d], s_sh[d]), 0.f);
            *reinterpret_cast<float4*>(out + obase + (size_t)d * NN * KK) = o;
        }
#pragma unroll
        for (int d = 0; d < DD; d++) {
            float fv = features[((size_t)b * DD + d) * NN + n];
            float4 o = {fv, fv, fv, fv};
            *reinterpret_cast<float4*>(out + obase + (size_t)(DD + d) * NN * KK) = o;
        }
    }
}

extern "C" void kernel_launch(void* const* d_in, const int* in_sizes, int n_in,
                              void* d_out, int out_size) {
    const float* coords   = (const float*)d_in[0];
    const float* features = (const float*)d_in[1];
    const int*   knn_idx  = (const int*)d_in[2];
    const float* knn_dist = (const float*)d_in[3];
    const int*   mask     = (const int*)d_in[4];
    const float* conv_w   = (const float*)d_in[5];
    const float* conv_b   = (const float*)d_in[6];
    const float* bn_gamma = (const float*)d_in[7];
    const float* bn_beta  = (const float*)d_in[8];
    float*       out      = (float*)d_out;

    k_fused<<<NBLK, TPB>>>(coords, features, knn_idx, knn_dist, mask,
                           conv_w, conv_b, bn_gamma, bn_beta, out);
}

// round 6
// speedup vs baseline: 1.5344x; 1.5344x over previous
#include <cuda_runtime.h>
#include <math_constants.h>

// Problem constants (fixed by the reference setup)
#define BB   4
#define NN   32768
#define KK   16
#define DD   8
#define TOT  (BB * NN * KK)        // 2,097,152 per channel
#define GRPS (TOT / 4)             // 524,288 groups of 4 along K
#define TPB  256
#define NBLK1 592                  // 148 SMs x 4 blocks: co-resident (64-reg cap ok for k1)
#define NT1  (NBLK1 * TPB)
#define NBLK2 (GRPS / TPB)         // 2048 blocks for pass2
#define EPSF 1e-6f

// Device-global scratch (no allocation allowed)
__device__ double g_sum[DD];
__device__ double g_sqs[DD];
__device__ float  g_scale[DD];
__device__ float  g_shift[DD];
__device__ unsigned int g_ctrA;    // barrier counter (monotone, replay-safe)
__device__ unsigned int g_ctrB;    // completion counter (monotone)
__device__ volatile unsigned int g_relA;
__device__ float4 g_c4[BB * NN];   // repacked coords (2 MB, L2-resident)

__device__ __forceinline__ int clamp_idx(int v) {
    v = v < 0 ? 0 : v;
    return v >= NN ? NN - 1 : v;
}

// ---------------- Kernel 1: repack + barrier + BN statistics ----------------
__global__ void __launch_bounds__(TPB, 4) k1_repack_stats(
    const float* __restrict__ coords,      // (B,N,3)
    const int* __restrict__ knn_idx,       // (B,N,K) int32
    const float* __restrict__ knn_dist,    // (B,N,K)
    const int* __restrict__ mask,          // (B,N)
    const float* __restrict__ conv_w,      // (D,10)
    const float* __restrict__ conv_b,      // (D)
    const float* __restrict__ bn_gamma,
    const float* __restrict__ bn_beta)
{
    __shared__ float s_wn0[DD], s_wn1[DD], s_wn2[DD], s_wdd[DD];
    __shared__ float s_wc0[DD], s_wc1[DD], s_wc2[DD], s_b[DD];
    __shared__ float s_part[TPB / 32][2 * DD];

    const int tid = threadIdx.x;
    const int gid = blockIdx.x * TPB + tid;

    // Phase 0: fold weights -> shared; block 0 zeroes the FP64 sums; repack coords.
    if (tid < DD) {
        const float* w = conv_w + tid * 10;
        float w0=w[0], w1=w[1], w2=w[2], w3=w[3], w4=w[4];
        float w5=w[5], w6=w[6], w7=w[7], w8=w[8];
        s_wn0[tid] = w3 - w6;  s_wn1[tid] = w4 - w7;  s_wn2[tid] = w5 - w8;
        s_wdd[tid] = w[9];
        s_wc0[tid] = w0 + w6;  s_wc1[tid] = w1 + w7;  s_wc2[tid] = w2 + w8;
        s_b[tid]   = conv_b[tid];
    }
    if (blockIdx.x == 0 && tid < DD) {
        g_sum[tid] = 0.0;
        g_sqs[tid] = 0.0;
    }
    if (gid < BB * NN) {
        float x = coords[3 * gid + 0];
        float y = coords[3 * gid + 1];
        float z = coords[3 * gid + 2];
        g_c4[gid] = make_float4(x, y, z, 0.f);
    }

    // Barrier A: all repack writes + sum zeroing visible before gathers.
    __threadfence();
    __syncthreads();
    if (tid == 0) {
        unsigned prev = atomicAdd(&g_ctrA, 1u);
        unsigned target = prev - (prev % NBLK1) + NBLK1;
        if (prev % NBLK1 == NBLK1 - 1) {
            g_relA = target;
        } else {
            while (g_relA < target) __nanosleep(64);
        }
    }
    __syncthreads();

    // Phase 1: grid-stride statistics.
    float s[DD], q[DD];
#pragma unroll
    for (int d = 0; d < DD; d++) { s[d] = 0.f; q[d] = 0.f; }

#pragma unroll 1
    for (int g = gid; g < GRPS; g += NT1) {
        const int e0 = g * 4;
        const int b  = e0 >> 19;            // / (NN*KK)
        const int rm = e0 & ((NN * KK) - 1);
        const int n  = rm >> 4;             // / KK

        const float4 c = g_c4[b * NN + n];

        int4 iv = *reinterpret_cast<const int4*>(knn_idx + e0);
        int j0 = clamp_idx(iv.x), j1 = clamp_idx(iv.y);
        int j2 = clamp_idx(iv.z), j3 = clamp_idx(iv.w);

        float4 d4 = *reinterpret_cast<const float4*>(knn_dist + e0);
        float dv0 = d4.x, dv1 = d4.y, dv2 = d4.z, dv3 = d4.w;
        if (mask[b * NN + n] == 0) {
            dv0 = dv1 = dv2 = dv3 = CUDART_INF_F;
        }

        float4 p0 = g_c4[b * NN + j0];
        float4 p1 = g_c4[b * NN + j1];
        float4 p2 = g_c4[b * NN + j2];
        float4 p3 = g_c4[b * NN + j3];

#pragma unroll
        for (int d = 0; d < DD; d++) {
            float base = s_b[d] + s_wc0[d]*c.x + s_wc1[d]*c.y + s_wc2[d]*c.z;
            float x0 = base + s_wn0[d]*p0.x + s_wn1[d]*p0.y + s_wn2[d]*p0.z + s_wdd[d]*dv0;
            float x1 = base + s_wn0[d]*p1.x + s_wn1[d]*p1.y + s_wn2[d]*p1.z + s_wdd[d]*dv1;
            float x2 = base + s_wn0[d]*p2.x + s_wn1[d]*p2.y + s_wn2[d]*p2.z + s_wdd[d]*dv2;
            float x3 = base + s_wn0[d]*p3.x + s_wn1[d]*p3.y + s_wn2[d]*p3.z + s_wdd[d]*dv3;
            s[d] += (x0 + x1) + (x2 + x3);
            q[d] = fmaf(x0, x0, q[d]);
            q[d] = fmaf(x1, x1, q[d]);
            q[d] = fmaf(x2, x2, q[d]);
            q[d] = fmaf(x3, x3, q[d]);
        }
    }

    // Block reduction -> double atomics.
#pragma unroll
    for (int d = 0; d < DD; d++) {
#pragma unroll
        for (int o = 16; o > 0; o >>= 1) {
            s[d] += __shfl_xor_sync(0xFFFFFFFFu, s[d], o);
            q[d] += __shfl_xor_sync(0xFFFFFFFFu, q[d], o);
        }
    }
    const int warp = tid >> 5;
    const int lane = tid & 31;
    if (lane == 0) {
#pragma unroll
        for (int d = 0; d < DD; d++) {
            s_part[warp][d]      = s[d];
            s_part[warp][DD + d] = q[d];
        }
    }
    __syncthreads();
    if (tid < 2 * DD) {
        float acc = 0.f;
#pragma unroll
        for (int w = 0; w < TPB / 32; w++) acc += s_part[w][tid];
        if (tid < DD)
            atomicAdd(&g_sum[tid], (double)acc);
        else
            atomicAdd(&g_sqs[tid - DD], (double)acc);
    }

    // Completion counter: LAST arriver finalizes BN affine params alone.
    // No release wait — everyone else just exits; the kernel boundary
    // publishes g_scale/g_shift to pass 2.
    __threadfence();
    __syncthreads();
    if (tid == 0) {
        unsigned prev = atomicAdd(&g_ctrB, 1u);
        if (prev % NBLK1 == NBLK1 - 1) {
            for (int d = 0; d < DD; d++) {
                double sm = ((volatile double*)g_sum)[d];
                double sq = ((volatile double*)g_sqs)[d];
                double mean = sm * (1.0 / (double)TOT);
                double var  = sq * (1.0 / (double)TOT) - mean * mean;
                float rstd  = rsqrtf((float)var + EPSF);
                float sc    = bn_gamma[d] * rstd;
                g_scale[d]  = sc;
                g_shift[d]  = bn_beta[d] - (float)mean * sc;
            }
        }
    }
}

// ---------------- Kernel 2: write the 128 MB output (pure fp32) ----------------
__global__ void __launch_bounds__(TPB) k2_write(
    const float* __restrict__ features,    // (B,D,N,1)
    const int* __restrict__ knn_idx,
    const float* __restrict__ knn_dist,
    const int* __restrict__ mask,
    const float* __restrict__ conv_w,
    const float* __restrict__ conv_b,
    float* __restrict__ out)               // (B,2D,N,K)
{
    __shared__ float s_wn0[DD], s_wn1[DD], s_wn2[DD], s_wdd[DD];
    __shared__ float s_wc0[DD], s_wc1[DD], s_wc2[DD], s_b[DD];
    __shared__ float s_sc[DD], s_sh[DD];

    const int tid = threadIdx.x;
    if (tid < DD) {
        const float* w = conv_w + tid * 10;
        float w0=w[0], w1=w[1], w2=w[2], w3=w[3], w4=w[4];
        float w5=w[5], w6=w[6], w7=w[7], w8=w[8];
        s_wn0[tid] = w3 - w6;  s_wn1[tid] = w4 - w7;  s_wn2[tid] = w5 - w8;
        s_wdd[tid] = w[9];
        s_wc0[tid] = w0 + w6;  s_wc1[tid] = w1 + w7;  s_wc2[tid] = w2 + w8;
        s_b[tid]   = conv_b[tid];
        s_sc[tid]  = g_scale[tid];
        s_sh[tid]  = g_shift[tid];
    }
    __syncthreads();

    const int g  = blockIdx.x * TPB + tid;
    const int e0 = g * 4;
    const int b  = e0 >> 19;
    const int rm = e0 & ((NN * KK) - 1);
    const int n  = rm >> 4;
    const int k0 = rm & (KK - 1);

    const float4 c = g_c4[b * NN + n];

    int4 iv = *reinterpret_cast<const int4*>(knn_idx + e0);
    int j0 = clamp_idx(iv.x), j1 = clamp_idx(iv.y);
    int j2 = clamp_idx(iv.z), j3 = clamp_idx(iv.w);

    float4 d4 = *reinterpret_cast<const float4*>(knn_dist + e0);
    float dv0 = d4.x, dv1 = d4.y, dv2 = d4.z, dv3 = d4.w;
    if (mask[b * NN + n] == 0) {
        dv0 = dv1 = dv2 = dv3 = CUDART_INF_F;
    }

    float4 p0 = g_c4[b * NN + j0];
    float4 p1 = g_c4[b * NN + j1];
    float4 p2 = g_c4[b * NN + j2];
    float4 p3 = g_c4[b * NN + j3];

    const size_t obase = ((size_t)b * (2 * DD)) * NN * KK + (size_t)n * KK + k0;
#pragma unroll
    for (int d = 0; d < DD; d++) {
        float base = s_b[d] + s_wc0[d]*c.x + s_wc1[d]*c.y + s_wc2[d]*c.z;
        float x0 = base + s_wn0[d]*p0.x + s_wn1[d]*p0.y + s_wn2[d]*p0.z + s_wdd[d]*dv0;
        float x1 = base + s_wn0[d]*p1.x + s_wn1[d]*p1.y + s_wn2[d]*p1.z + s_wdd[d]*dv1;
        float x2 = base + s_wn0[d]*p2.x + s_wn1[d]*p2.y + s_wn2[d]*p2.z + s_wdd[d]*dv2;
        float x3 = base + s_wn0[d]*p3.x + s_wn1[d]*p3.y + s_wn2[d]*p3.z + s_wdd[d]*dv3;
        float4 o;
        o.x = fmaxf(fmaf(x0, s_sc[d], s_sh[d]), 0.f);
        o.y = fmaxf(fmaf(x1, s_sc[d], s_sh[d]), 0.f);
        o.z = fmaxf(fmaf(x2, s_sc[d], s_sh[d]), 0.f);
        o.w = fmaxf(fmaf(x3, s_sc[d], s_sh[d]), 0.f);
        *reinterpret_cast<float4*>(out + obase + (size_t)d * NN * KK) = o;
    }
#pragma unroll
    for (int d = 0; d < DD; d++) {
        float fv = features[((size_t)b * DD + d) * NN + n];
        float4 o = {fv, fv, fv, fv};
        *reinterpret_cast<float4*>(out + obase + (size_t)(DD + d) * NN * KK) = o;
    }
}

extern "C" void kernel_launch(void* const* d_in, const int* in_sizes, int n_in,
                              void* d_out, int out_size) {
    const float* coords   = (const float*)d_in[0];
    const float* features = (const float*)d_in[1];
    const int*   knn_idx  = (const int*)d_in[2];
    const float* knn_dist = (const float*)d_in[3];
    const int*   mask     = (const int*)d_in[4];
    const float* conv_w   = (const float*)d_in[5];
    const float* conv_b   = (const float*)d_in[6];
    const float* bn_gamma = (const float*)d_in[7];
    const float* bn_beta  = (const float*)d_in[8];
    float*       out      = (float*)d_out;

    k1_repack_stats<<<NBLK1, TPB>>>(coords, knn_idx, knn_dist, mask,
                                    conv_w, conv_b, bn_gamma, bn_beta);
    k2_write<<<NBLK2, TPB>>>(features, knn_idx, knn_dist, mask,
                             conv_w, conv_b, out);
}

// round 11
// speedup vs baseline: 1.9500x; 1.2708x over previous
#include <cuda_runtime.h>
#include <math_constants.h>

// Problem constants (fixed by the reference setup)
#define BB   4
#define NN   32768
#define KK   16
#define DD   8
#define TOT  (BB * NN * KK)        // 2,097,152 per channel
#define GRPS (TOT / 4)             // 524,288 groups of 4 along K
#define TPB  256
#define NBLK1 296                  // 148 SMs x 2 blocks (128-reg cap => co-resident)
#define NT1  (NBLK1 * TPB)         // 75,776 threads
#define NBLK2 (GRPS / TPB)         // 2048 blocks
#define FITERS 8                   // feature kernel: 8 float4 slots per thread
#define EPSF 1e-6f

// Device-global scratch (no allocation allowed)
__device__ double g_sum[DD];
__device__ double g_sqs[DD];
__device__ float  g_scale[DD];
__device__ float  g_shift[DD];
__device__ unsigned int g_ctrA;    // barrier counter (monotone, replay-safe)
__device__ unsigned int g_ctrB;    // completion counter (monotone)
__device__ volatile unsigned int g_relA;
__device__ float4 g_c4[BB * NN];   // repacked coords (2 MB, L2-resident)

__device__ __forceinline__ int clamp_idx(int v) {
    v = v < 0 ? 0 : v;
    return v >= NN ? NN - 1 : v;
}

// ------------- Kernel 1: repack + grid barrier + BN statistics -------------
__global__ void __launch_bounds__(TPB, 2) k1_repack_stats(
    const float* __restrict__ coords,      // (B,N,3)
    const int* __restrict__ knn_idx,       // (B,N,K) int32
    const float* __restrict__ knn_dist,    // (B,N,K)
    const int* __restrict__ mask,          // (B,N)
    const float* __restrict__ conv_w,      // (D,10)
    const float* __restrict__ conv_b,      // (D)
    const float* __restrict__ bn_gamma,
    const float* __restrict__ bn_beta)
{
    __shared__ float s_wn0[DD], s_wn1[DD], s_wn2[DD], s_wdd[DD];
    __shared__ float s_wc0[DD], s_wc1[DD], s_wc2[DD], s_b[DD];
    __shared__ float s_part[TPB / 32][2 * DD];

    const int tid = threadIdx.x;
    const int gid = blockIdx.x * TPB + tid;

    if (tid < DD) {
        const float* w = conv_w + tid * 10;
        float w0=w[0], w1=w[1], w2=w[2], w3=w[3], w4=w[4];
        float w5=w[5], w6=w[6], w7=w[7], w8=w[8];
        s_wn0[tid] = w3 - w6;  s_wn1[tid] = w4 - w7;  s_wn2[tid] = w5 - w8;
        s_wdd[tid] = w[9];
        s_wc0[tid] = w0 + w6;  s_wc1[tid] = w1 + w7;  s_wc2[tid] = w2 + w8;
        s_b[tid]   = conv_b[tid];
    }
    if (blockIdx.x == 0 && tid < DD) {
        g_sum[tid] = 0.0;
        g_sqs[tid] = 0.0;
    }
    // Repack coords (grid-stride: 131072 points over 75776 threads)
#pragma unroll 1
    for (int i = gid; i < BB * NN; i += NT1) {
        float x = coords[3 * i + 0];
        float y = coords[3 * i + 1];
        float z = coords[3 * i + 2];
        g_c4[i] = make_float4(x, y, z, 0.f);
    }

    // Barrier: all repack writes + sum zeroing visible before gathers.
    __threadfence();
    __syncthreads();
    if (tid == 0) {
        unsigned prev = atomicAdd(&g_ctrA, 1u);
        unsigned target = prev - (prev % NBLK1) + NBLK1;
        if (prev % NBLK1 == NBLK1 - 1) {
            g_relA = target;
        } else {
            while (g_relA < target) __nanosleep(64);
        }
    }
    __syncthreads();

    // Grid-stride statistics.
    float s[DD], q[DD];
#pragma unroll
    for (int d = 0; d < DD; d++) { s[d] = 0.f; q[d] = 0.f; }

#pragma unroll 1
    for (int g = gid; g < GRPS; g += NT1) {
        const int e0 = g * 4;
        const int b  = e0 >> 19;            // / (NN*KK)
        const int rm = e0 & ((NN * KK) - 1);
        const int n  = rm >> 4;             // / KK

        const float4 c = g_c4[b * NN + n];

        int4 iv = *reinterpret_cast<const int4*>(knn_idx + e0);
        int j0 = clamp_idx(iv.x), j1 = clamp_idx(iv.y);
        int j2 = clamp_idx(iv.z), j3 = clamp_idx(iv.w);

        float4 d4 = *reinterpret_cast<const float4*>(knn_dist + e0);
        float dv0 = d4.x, dv1 = d4.y, dv2 = d4.z, dv3 = d4.w;
        if (mask[b * NN + n] == 0) {
            dv0 = dv1 = dv2 = dv3 = CUDART_INF_F;
        }

        float4 p0 = g_c4[b * NN + j0];
        float4 p1 = g_c4[b * NN + j1];
        float4 p2 = g_c4[b * NN + j2];
        float4 p3 = g_c4[b * NN + j3];

#pragma unroll
        for (int d = 0; d < DD; d++) {
            float base = s_b[d] + s_wc0[d]*c.x + s_wc1[d]*c.y + s_wc2[d]*c.z;
            float x0 = base + s_wn0[d]*p0.x + s_wn1[d]*p0.y + s_wn2[d]*p0.z + s_wdd[d]*dv0;
            float x1 = base + s_wn0[d]*p1.x + s_wn1[d]*p1.y + s_wn2[d]*p1.z + s_wdd[d]*dv1;
            float x2 = base + s_wn0[d]*p2.x + s_wn1[d]*p2.y + s_wn2[d]*p2.z + s_wdd[d]*dv2;
            float x3 = base + s_wn0[d]*p3.x + s_wn1[d]*p3.y + s_wn2[d]*p3.z + s_wdd[d]*dv3;
            s[d] += (x0 + x1) + (x2 + x3);
            q[d] = fmaf(x0, x0, q[d]);
            q[d] = fmaf(x1, x1, q[d]);
            q[d] = fmaf(x2, x2, q[d]);
            q[d] = fmaf(x3, x3, q[d]);
        }
    }

    // Block reduction -> double atomics.
#pragma unroll
    for (int d = 0; d < DD; d++) {
#pragma unroll
        for (int o = 16; o > 0; o >>= 1) {
            s[d] += __shfl_xor_sync(0xFFFFFFFFu, s[d], o);
            q[d] += __shfl_xor_sync(0xFFFFFFFFu, q[d], o);
        }
    }
    const int warp = tid >> 5;
    const int lane = tid & 31;
    if (lane == 0) {
#pragma unroll
        for (int d = 0; d < DD; d++) {
            s_part[warp][d]      = s[d];
            s_part[warp][DD + d] = q[d];
        }
    }
    __syncthreads();
    if (tid < 2 * DD) {
        float acc = 0.f;
#pragma unroll
        for (int w = 0; w < TPB / 32; w++) acc += s_part[w][tid];
        if (tid < DD)
            atomicAdd(&g_sum[tid], (double)acc);
        else
            atomicAdd(&g_sqs[tid - DD], (double)acc);
    }

    // Completion counter: LAST arriver finalizes BN params alone; others exit.
    __threadfence();
    __syncthreads();
    if (tid == 0) {
        unsigned prev = atomicAdd(&g_ctrB, 1u);
        if (prev % NBLK1 == NBLK1 - 1) {
            for (int d = 0; d < DD; d++) {
                double sm = ((volatile double*)g_sum)[d];
                double sq = ((volatile double*)g_sqs)[d];
                double mean = sm * (1.0 / (double)TOT);
                double var  = sq * (1.0 / (double)TOT) - mean * mean;
                float rstd  = rsqrtf((float)var + EPSF);
                float sc    = bn_gamma[d] * rstd;
                g_scale[d]  = sc;
                g_shift[d]  = bn_beta[d] - (float)mean * sc;
            }
        }
    }
}

// ------------- Kernel 2a: conv+BN+relu channels [0..7] (64 MB) -------------
__global__ void __launch_bounds__(TPB, 3) k2_conv(
    const int* __restrict__ knn_idx,
    const float* __restrict__ knn_dist,
    const int* __restrict__ mask,
    const float* __restrict__ conv_w,
    const float* __restrict__ conv_b,
    float* __restrict__ out)               // (B,2D,N,K)
{
    __shared__ float s_wn0[DD], s_wn1[DD], s_wn2[DD], s_wdd[DD];
    __shared__ float s_wc0[DD], s_wc1[DD], s_wc2[DD], s_b[DD];
    __shared__ float s_sc[DD], s_sh[DD];

    const int tid = threadIdx.x;
    if (tid < DD) {
        const float* w = conv_w + tid * 10;
        float w0=w[0], w1=w[1], w2=w[2], w3=w[3], w4=w[4];
        float w5=w[5], w6=w[6], w7=w[7], w8=w[8];
        s_wn0[tid] = w3 - w6;  s_wn1[tid] = w4 - w7;  s_wn2[tid] = w5 - w8;
        s_wdd[tid] = w[9];
        s_wc0[tid] = w0 + w6;  s_wc1[tid] = w1 + w7;  s_wc2[tid] = w2 + w8;
        s_b[tid]   = conv_b[tid];
        s_sc[tid]  = g_scale[tid];
        s_sh[tid]  = g_shift[tid];
    }
    __syncthreads();

    const int g  = blockIdx.x * TPB + tid;
    const int e0 = g * 4;
    const int b  = e0 >> 19;
    const int rm = e0 & ((NN * KK) - 1);
    const int n  = rm >> 4;
    const int k0 = rm & (KK - 1);

    const float4 c = g_c4[b * NN + n];

    int4 iv = *reinterpret_cast<const int4*>(knn_idx + e0);
    int j0 = clamp_idx(iv.x), j1 = clamp_idx(iv.y);
    int j2 = clamp_idx(iv.z), j3 = clamp_idx(iv.w);

    float4 d4 = *reinterpret_cast<const float4*>(knn_dist + e0);
    float dv0 = d4.x, dv1 = d4.y, dv2 = d4.z, dv3 = d4.w;
    if (mask[b * NN + n] == 0) {
        dv0 = dv1 = dv2 = dv3 = CUDART_INF_F;
    }

    float4 p0 = g_c4[b * NN + j0];
    float4 p1 = g_c4[b * NN + j1];
    float4 p2 = g_c4[b * NN + j2];
    float4 p3 = g_c4[b * NN + j3];

    const size_t obase = ((size_t)b * (2 * DD)) * NN * KK + (size_t)n * KK + k0;
#pragma unroll
    for (int d = 0; d < DD; d++) {
        float base = s_b[d] + s_wc0[d]*c.x + s_wc1[d]*c.y + s_wc2[d]*c.z;
        float x0 = base + s_wn0[d]*p0.x + s_wn1[d]*p0.y + s_wn2[d]*p0.z + s_wdd[d]*dv0;
        float x1 = base + s_wn0[d]*p1.x + s_wn1[d]*p1.y + s_wn2[d]*p1.z + s_wdd[d]*dv1;
        float x2 = base + s_wn0[d]*p2.x + s_wn1[d]*p2.y + s_wn2[d]*p2.z + s_wdd[d]*dv2;
        float x3 = base + s_wn0[d]*p3.x + s_wn1[d]*p3.y + s_wn2[d]*p3.z + s_wdd[d]*dv3;
        float4 o;
        o.x = fmaxf(fmaf(x0, s_sc[d], s_sh[d]), 0.f);
        o.y = fmaxf(fmaf(x1, s_sc[d], s_sh[d]), 0.f);
        o.z = fmaxf(fmaf(x2, s_sc[d], s_sh[d]), 0.f);
        o.w = fmaxf(fmaf(x3, s_sc[d], s_sh[d]), 0.f);
        *reinterpret_cast<float4*>(out + obase + (size_t)d * NN * KK) = o;
    }
}

// ------------- Kernel 2b: feature broadcast channels [8..15] (64 MB) -------------
// 2048 blocks x 256 threads x FITERS(8) float4 slots = 4,194,304 slots = full coverage.
__global__ void __launch_bounds__(TPB) k2_feat(
    const float* __restrict__ features,    // (B,D,N,1)
    float* __restrict__ out)               // (B,2D,N,K)
{
    const int t0 = blockIdx.x * TPB + threadIdx.x;
#pragma unroll
    for (int it = 0; it < FITERS; it++) {
        const int g = it * (NBLK2 * TPB) + t0;   // 0 .. 4,194,303 float4 slots
        // decode (b, d, n, k4): k4 in [0,4), n in [0,NN), d in [0,DD), b in [0,BB)
        const int k4 = g & 3;
        const int n  = (g >> 2) & (NN - 1);
        const int d  = (g >> 17) & (DD - 1);
        const int b  = g >> 20;
        float fv = features[((size_t)b * DD + d) * NN + n];
        float4 o = {fv, fv, fv, fv};
        const size_t off = ((size_t)b * (2 * DD) + (DD + d)) * NN * KK
                         + (size_t)n * KK + k4 * 4;
        *reinterpret_cast<float4*>(out + off) = o;
    }
}

extern "C" void kernel_launch(void* const* d_in, const int* in_sizes, int n_in,
                              void* d_out, int out_size) {
    const float* coords   = (const float*)d_in[0];
    const float* features = (const float*)d_in[1];
    const int*   knn_idx  = (const int*)d_in[2];
    const float* knn_dist = (const float*)d_in[3];
    const int*   mask     = (const int*)d_in[4];
    const float* conv_w   = (const float*)d_in[5];
    const float* conv_b   = (const float*)d_in[6];
    const float* bn_gamma = (const float*)d_in[7];
    const float* bn_beta  = (const float*)d_in[8];
    float*       out      = (float*)d_out;

    k1_repack_stats<<<NBLK1, TPB>>>(coords, knn_idx, knn_dist, mask,
                                    conv_w, conv_b, bn_gamma, bn_beta);
    k2_conv<<<NBLK2, TPB>>>(knn_idx, knn_dist, mask, conv_w, conv_b, out);
    k2_feat<<<NBLK2, TPB>>>(features, out);
}

// round 13
// speedup vs baseline: 2.0098x; 1.0307x over previous
#include <cuda_runtime.h>
#include <math_constants.h>

// Problem constants (fixed by the reference setup)
#define BB   4
#define NN   32768
#define KK   16
#define DD   8
#define TOT  (BB * NN * KK)        // 2,097,152 per channel
#define GRPS (TOT / 4)             // 524,288 groups of 4 along K
#define TPB  256
#define NBLKF 2048                 // feature kernel blocks (8 float4 slots/thread)
#define FITERS 8
#define NBLKS 296                  // stats kernel blocks (grid-stride, no residency req)
#define NTS  (NBLKS * TPB)
#define NBLKC (GRPS / TPB)         // 2048 conv blocks
#define EPSF 1e-6f

// Device-global scratch (no allocation allowed)
__device__ double g_sum[DD];
__device__ double g_sqs[DD];
__device__ float  g_scale[DD];
__device__ float  g_shift[DD];
__device__ unsigned int g_ctrB;    // completion counter (monotone, replay-safe)
__device__ float4 g_c4[BB * NN];   // repacked coords (2 MB, L2-resident)

__device__ __forceinline__ int clamp_idx(int v) {
    v = v < 0 ? 0 : v;
    return v >= NN ? NN - 1 : v;
}

// ---- Kernel 1: feature broadcast (channels 8..15, 64 MB) + coords repack + sum zero
// 2048 blocks x 256 threads x 8 float4 slots = full coverage of the feature half.
// Repack piggybacks on the first 131072 threads; zeroing on block 0.
// Ordering to consumers is via kernel boundaries (no barrier needed).
__global__ void __launch_bounds__(TPB) k_feat_repack(
    const float* __restrict__ features,    // (B,D,N,1)
    const float* __restrict__ coords,      // (B,N,3)
    float* __restrict__ out)               // (B,2D,N,K)
{
    const int t0 = blockIdx.x * TPB + threadIdx.x;   // 0 .. 524287
    if (blockIdx.x == 0 && threadIdx.x < DD) {
        g_sum[threadIdx.x] = 0.0;
        g_sqs[threadIdx.x] = 0.0;
    }
    if (t0 < BB * NN) {
        float x = coords[3 * t0 + 0];
        float y = coords[3 * t0 + 1];
        float z = coords[3 * t0 + 2];
        g_c4[t0] = make_float4(x, y, z, 0.f);
    }
#pragma unroll
    for (int it = 0; it < FITERS; it++) {
        const int g = it * (NBLKF * TPB) + t0;   // 0 .. 4,194,303 float4 slots
        const int k4 = g & 3;
        const int n  = (g >> 2) & (NN - 1);
        const int d  = (g >> 17) & (DD - 1);
        const int b  = g >> 20;
        float fv = features[((size_t)b * DD + d) * NN + n];
        float4 o = {fv, fv, fv, fv};
        const size_t off = ((size_t)b * (2 * DD) + (DD + d)) * NN * KK
                         + (size_t)n * KK + k4 * 4;
        *reinterpret_cast<float4*>(out + off) = o;
    }
}

// ---- Kernel 2: BN statistics (grid-stride, natural regs, no barrier) ----
// Last arriver at the monotone completion counter finalizes scale/shift alone.
__global__ void __launch_bounds__(TPB) k_stats(
    const int* __restrict__ knn_idx,       // (B,N,K) int32
    const float* __restrict__ knn_dist,    // (B,N,K)
    const int* __restrict__ mask,          // (B,N)
    const float* __restrict__ conv_w,      // (D,10)
    const float* __restrict__ conv_b,      // (D)
    const float* __restrict__ bn_gamma,
    const float* __restrict__ bn_beta)
{
    __shared__ float s_wn0[DD], s_wn1[DD], s_wn2[DD], s_wdd[DD];
    __shared__ float s_wc0[DD], s_wc1[DD], s_wc2[DD], s_b[DD];
    __shared__ float s_part[TPB / 32][2 * DD];

    const int tid = threadIdx.x;
    const int gid = blockIdx.x * TPB + tid;

    if (tid < DD) {
        const float* w = conv_w + tid * 10;
        float w0=w[0], w1=w[1], w2=w[2], w3=w[3], w4=w[4];
        float w5=w[5], w6=w[6], w7=w[7], w8=w[8];
        s_wn0[tid] = w3 - w6;  s_wn1[tid] = w4 - w7;  s_wn2[tid] = w5 - w8;
        s_wdd[tid] = w[9];
        s_wc0[tid] = w0 + w6;  s_wc1[tid] = w1 + w7;  s_wc2[tid] = w2 + w8;
        s_b[tid]   = conv_b[tid];
    }
    __syncthreads();

    float s[DD], q[DD];
#pragma unroll
    for (int d = 0; d < DD; d++) { s[d] = 0.f; q[d] = 0.f; }

#pragma unroll 1
    for (int g = gid; g < GRPS; g += NTS) {
        const int e0 = g * 4;
        const int b  = e0 >> 19;
        const int rm = e0 & ((NN * KK) - 1);
        const int n  = rm >> 4;

        const float4 c = g_c4[b * NN + n];

        int4 iv = *reinterpret_cast<const int4*>(knn_idx + e0);
        int j0 = clamp_idx(iv.x), j1 = clamp_idx(iv.y);
        int j2 = clamp_idx(iv.z), j3 = clamp_idx(iv.w);

        float4 d4 = *reinterpret_cast<const float4*>(knn_dist + e0);
        float dv0 = d4.x, dv1 = d4.y, dv2 = d4.z, dv3 = d4.w;
        if (mask[b * NN + n] == 0) {
            dv0 = dv1 = dv2 = dv3 = CUDART_INF_F;
        }

        float4 p0 = g_c4[b * NN + j0];
        float4 p1 = g_c4[b * NN + j1];
        float4 p2 = g_c4[b * NN + j2];
        float4 p3 = g_c4[b * NN + j3];

#pragma unroll
        for (int d = 0; d < DD; d++) {
            float base = s_b[d] + s_wc0[d]*c.x + s_wc1[d]*c.y + s_wc2[d]*c.z;
            float x0 = base + s_wn0[d]*p0.x + s_wn1[d]*p0.y + s_wn2[d]*p0.z + s_wdd[d]*dv0;
            float x1 = base + s_wn0[d]*p1.x + s_wn1[d]*p1.y + s_wn2[d]*p1.z + s_wdd[d]*dv1;
            float x2 = base + s_wn0[d]*p2.x + s_wn1[d]*p2.y + s_wn2[d]*p2.z + s_wdd[d]*dv2;
            float x3 = base + s_wn0[d]*p3.x + s_wn1[d]*p3.y + s_wn2[d]*p3.z + s_wdd[d]*dv3;
            s[d] += (x0 + x1) + (x2 + x3);
            q[d] = fmaf(x0, x0, q[d]);
            q[d] = fmaf(x1, x1, q[d]);
            q[d] = fmaf(x2, x2, q[d]);
            q[d] = fmaf(x3, x3, q[d]);
        }
    }

    // Block reduction -> double atomics.
#pragma unroll
    for (int d = 0; d < DD; d++) {
#pragma unroll
        for (int o = 16; o > 0; o >>= 1) {
            s[d] += __shfl_xor_sync(0xFFFFFFFFu, s[d], o);
            q[d] += __shfl_xor_sync(0xFFFFFFFFu, q[d], o);
        }
    }
    const int warp = tid >> 5;
    const int lane = tid & 31;
    if (lane == 0) {
#pragma unroll
        for (int d = 0; d < DD; d++) {
            s_part[warp][d]      = s[d];
            s_part[warp][DD + d] = q[d];
        }
    }
    __syncthreads();
    if (tid < 2 * DD) {
        float acc = 0.f;
#pragma unroll
        for (int w = 0; w < TPB / 32; w++) acc += s_part[w][tid];
        if (tid < DD)
            atomicAdd(&g_sum[tid], (double)acc);
        else
            atomicAdd(&g_sqs[tid - DD], (double)acc);
    }

    // Completion counter: LAST arriver finalizes BN params alone; others exit.
    __threadfence();
    __syncthreads();
    if (tid == 0) {
        unsigned prev = atomicAdd(&g_ctrB, 1u);
        if (prev % NBLKS == NBLKS - 1) {
            for (int d = 0; d < DD; d++) {
                double sm = ((volatile double*)g_sum)[d];
                double sq = ((volatile double*)g_sqs)[d];
                double mean = sm * (1.0 / (double)TOT);
                double var  = sq * (1.0 / (double)TOT) - mean * mean;
                float rstd  = rsqrtf((float)var + EPSF);
                float sc    = bn_gamma[d] * rstd;
                g_scale[d]  = sc;
                g_shift[d]  = bn_beta[d] - (float)mean * sc;
            }
        }
    }
}

// ---- Kernel 3: conv+BN+relu channels [0..7] (64 MB) ----
__global__ void __launch_bounds__(TPB, 3) k_conv(
    const int* __restrict__ knn_idx,
    const float* __restrict__ knn_dist,
    const int* __restrict__ mask,
    const float* __restrict__ conv_w,
    const float* __restrict__ conv_b,
    float* __restrict__ out)               // (B,2D,N,K)
{
    __shared__ float s_wn0[DD], s_wn1[DD], s_wn2[DD], s_wdd[DD];
    __shared__ float s_wc0[DD], s_wc1[DD], s_wc2[DD], s_b[DD];
    __shared__ float s_sc[DD], s_sh[DD];

    const int tid = threadIdx.x;
    if (tid < DD) {
        const float* w = conv_w + tid * 10;
        float w0=w[0], w1=w[1], w2=w[2], w3=w[3], w4=w[4];
        float w5=w[5], w6=w[6], w7=w[7], w8=w[8];
        s_wn0[tid] = w3 - w6;  s_wn1[tid] = w4 - w7;  s_wn2[tid] = w5 - w8;
        s_wdd[tid] = w[9];
        s_wc0[tid] = w0 + w6;  s_wc1[tid] = w1 + w7;  s_wc2[tid] = w2 + w8;
        s_b[tid]   = conv_b[tid];
        s_sc[tid]  = g_scale[tid];
        s_sh[tid]  = g_shift[tid];
    }
    __syncthreads();

    const int g  = blockIdx.x * TPB + tid;
    const int e0 = g * 4;
    const int b  = e0 >> 19;
    const int rm = e0 & ((NN * KK) - 1);
    const int n  = rm >> 4;
    const int k0 = rm & (KK - 1);

    const float4 c = g_c4[b * NN + n];

    int4 iv = *reinterpret_cast<const int4*>(knn_idx + e0);
    int j0 = clamp_idx(iv.x), j1 = clamp_idx(iv.y);
    int j2 = clamp_idx(iv.z), j3 = clamp_idx(iv.w);

    float4 d4 = *reinterpret_cast<const float4*>(knn_dist + e0);
    float dv0 = d4.x, dv1 = d4.y, dv2 = d4.z, dv3 = d4.w;
    if (mask[b * NN + n] == 0) {
        dv0 = dv1 = dv2 = dv3 = CUDART_INF_F;
    }

    float4 p0 = g_c4[b * NN + j0];
    float4 p1 = g_c4[b * NN + j1];
    float4 p2 = g_c4[b * NN + j2];
    float4 p3 = g_c4[b * NN + j3];

    const size_t obase = ((size_t)b * (2 * DD)) * NN * KK + (size_t)n * KK + k0;
#pragma unroll
    for (int d = 0; d < DD; d++) {
        float base = s_b[d] + s_wc0[d]*c.x + s_wc1[d]*c.y + s_wc2[d]*c.z;
        float x0 = base + s_wn0[d]*p0.x + s_wn1[d]*p0.y + s_wn2[d]*p0.z + s_wdd[d]*dv0;
        float x1 = base + s_wn0[d]*p1.x + s_wn1[d]*p1.y + s_wn2[d]*p1.z + s_wdd[d]*dv1;
        float x2 = base + s_wn0[d]*p2.x + s_wn1[d]*p2.y + s_wn2[d]*p2.z + s_wdd[d]*dv2;
        float x3 = base + s_wn0[d]*p3.x + s_wn1[d]*p3.y + s_wn2[d]*p3.z + s_wdd[d]*dv3;
        float4 o;
        o.x = fmaxf(fmaf(x0, s_sc[d], s_sh[d]), 0.f);
        o.y = fmaxf(fmaf(x1, s_sc[d], s_sh[d]), 0.f);
        o.z = fmaxf(fmaf(x2, s_sc[d], s_sh[d]), 0.f);
        o.w = fmaxf(fmaf(x3, s_sc[d], s_sh[d]), 0.f);
        *reinterpret_cast<float4*>(out + obase + (size_t)d * NN * KK) = o;
    }
}

extern "C" void kernel_launch(void* const* d_in, const int* in_sizes, int n_in,
                              void* d_out, int out_size) {
    const float* coords   = (const float*)d_in[0];
    const float* features = (const float*)d_in[1];
    const int*   knn_idx  = (const int*)d_in[2];
    const float* knn_dist = (const float*)d_in[3];
    const int*   mask     = (const int*)d_in[4];
    const float* conv_w   = (const float*)d_in[5];
    const float* conv_b   = (const float*)d_in[6];
    const float* bn_gamma = (const float*)d_in[7];
    const float* bn_beta  = (const float*)d_in[8];
    float*       out      = (float*)d_out;

    // Order matters: feat+repack publishes g_c4 & zeroed sums; stats publishes
    // scale/shift; conv consumes both. All ordering via kernel boundaries.
    k_feat_repack<<<NBLKF, TPB>>>(features, coords, out);
    k_stats<<<NBLKS, TPB>>>(knn_idx, knn_dist, mask, conv_w, conv_b,
                            bn_gamma, bn_beta);
    k_conv<<<NBLKC, TPB>>>(knn_idx, knn_dist, mask, conv_w, conv_b, out);
}